// round 12
// baseline (speedup 1.0000x reference)
#include <cuda_runtime.h>
#include <cuda_fp16.h>
#include <math.h>
#include <stdint.h>

#define HEADS   12
#define DH      64
#define SEQ     2048
#define BATCH   4
#define DMODEL  768
#define QKVW    2304      // 3 * 768
// softmax scale folded with log2(e): exp(x*SCALE) = exp2(x * SCL2)
#define SCL2    0.1803368801111244f   // 0.125 * log2(e)

// Scratch (device globals; no allocations allowed)
__device__ __half g_xh  [(size_t)BATCH * SEQ * DMODEL];
__device__ __half g_wqh [(size_t)DMODEL * QKVW];
__device__ __half g_woh [(size_t)DMODEL * DMODEL];
__device__ __half g_qkv [(size_t)BATCH * SEQ * QKVW];
__device__ __half g_attn[(size_t)BATCH * SEQ * DMODEL];

// ---------------------------------------------------------------------------
// helpers
// ---------------------------------------------------------------------------
__device__ __forceinline__ void mma_f16(float c[4],
                                        uint32_t a0, uint32_t a1,
                                        uint32_t a2, uint32_t a3,
                                        uint32_t b0, uint32_t b1) {
    asm volatile(
        "mma.sync.aligned.m16n8k16.row.col.f32.f16.f16.f32 "
        "{%0,%1,%2,%3}, {%4,%5,%6,%7}, {%8,%9}, {%0,%1,%2,%3};\n"
        : "+f"(c[0]), "+f"(c[1]), "+f"(c[2]), "+f"(c[3])
        : "r"(a0), "r"(a1), "r"(a2), "r"(a3), "r"(b0), "r"(b1));
}

__device__ __forceinline__ void ldsm_x4(uint32_t& r0, uint32_t& r1,
                                        uint32_t& r2, uint32_t& r3,
                                        uint32_t addr) {
    asm volatile(
        "ldmatrix.sync.aligned.m8n8.x4.shared.b16 {%0,%1,%2,%3}, [%4];"
        : "=r"(r0), "=r"(r1), "=r"(r2), "=r"(r3) : "r"(addr));
}

__device__ __forceinline__ void ldsm_x4_t(uint32_t& r0, uint32_t& r1,
                                          uint32_t& r2, uint32_t& r3,
                                          uint32_t addr) {
    asm volatile(
        "ldmatrix.sync.aligned.m8n8.x4.trans.shared.b16 {%0,%1,%2,%3}, [%4];"
        : "=r"(r0), "=r"(r1), "=r"(r2), "=r"(r3) : "r"(addr));
}

__device__ __forceinline__ void cp_async16(uint32_t dst_smem, const void* src) {
    asm volatile("cp.async.cg.shared.global [%0], [%1], 16;"
                 :: "r"(dst_smem), "l"(src));
}
__device__ __forceinline__ void cp_commit() {
    asm volatile("cp.async.commit_group;");
}
__device__ __forceinline__ void cp_wait_all() {
    asm volatile("cp.async.wait_group 0;");
}

// packed fp16x2 exp2: one MUFU op for two values
__device__ __forceinline__ uint32_t h2exp2_pk(float lo, float hi) {
    __half2 h = __floats2half2_rn(lo, hi);
    uint32_t in = *reinterpret_cast<uint32_t*>(&h);
    uint32_t out;
    asm("ex2.approx.f16x2 %0, %1;" : "=r"(out) : "r"(in));
    return out;
}

// ---------------------------------------------------------------------------
// fp32 -> fp16 elementwise (n % 4 == 0)
// ---------------------------------------------------------------------------
__global__ __launch_bounds__(256)
void f32_to_f16(const float* __restrict__ src, __half* __restrict__ dst, int n) {
    int i = (blockIdx.x * 256 + threadIdx.x) * 4;
    if (i < n) {
        float4 v = *(const float4*)(src + i);
        *(__half2*)(dst + i)     = __floats2half2_rn(v.x, v.y);
        *(__half2*)(dst + i + 2) = __floats2half2_rn(v.z, v.w);
    }
}

// ---------------------------------------------------------------------------
// GEMM (fp16 in, fp32 accum): UNCHANGED round-10 structure (known-good).
// ---------------------------------------------------------------------------
#define BM 128
#define BN 128
#define BK 32
#define AW 40     // halves
#define BW 136    // halves

__global__ __launch_bounds__(256)
void gemm_f16(const __half* __restrict__ A, const __half* __restrict__ B,
              const float* __restrict__ bias, void* __restrict__ Cout,
              int M, int N, int K, int out_half) {
    __shared__ __half As[BM * AW];
    __shared__ __half Bs[BK * BW];

    int tid  = threadIdx.x;
    int lane = tid & 31, wid = tid >> 5;
    int wm = (wid >> 2) * 64;
    int wn = (wid & 3) * 32;
    int g  = lane >> 2, q = lane & 3;
    uint32_t lr = lane & 15, lhi = (lane >> 4) * 8;

    uint32_t as_u32 = (uint32_t)__cvta_generic_to_shared(As);
    uint32_t bs_u32 = (uint32_t)__cvta_generic_to_shared(Bs);

    int row0 = blockIdx.y * BM, col0 = blockIdx.x * BN;

    int ar = tid >> 1, ac = (tid & 1) << 4;
    int br = tid >> 3, bc = (tid & 7) << 4;

    float acc[4][4][4] = {};
    uint4 pa0, pa1, pb0, pb1;

    pa0 = *(const uint4*)(A + (size_t)(row0 + ar) * K + ac);
    pa1 = *(const uint4*)(A + (size_t)(row0 + ar) * K + ac + 8);
    pb0 = *(const uint4*)(B + (size_t)br * N + col0 + bc);
    pb1 = *(const uint4*)(B + (size_t)br * N + col0 + bc + 8);

    for (int k0 = 0; k0 < K; k0 += BK) {
        *(uint4*)&As[ar * AW + ac]     = pa0;
        *(uint4*)&As[ar * AW + ac + 8] = pa1;
        *(uint4*)&Bs[br * BW + bc]     = pb0;
        *(uint4*)&Bs[br * BW + bc + 8] = pb1;
        __syncthreads();

        int kn = k0 + BK;
        if (kn < K) {
            pa0 = *(const uint4*)(A + (size_t)(row0 + ar) * K + kn + ac);
            pa1 = *(const uint4*)(A + (size_t)(row0 + ar) * K + kn + ac + 8);
            pb0 = *(const uint4*)(B + (size_t)(kn + br) * N + col0 + bc);
            pb1 = *(const uint4*)(B + (size_t)(kn + br) * N + col0 + bc + 8);
        }

        #pragma unroll
        for (int ks = 0; ks < BK / 16; ks++) {
            int kk = ks * 16;
            uint32_t af[4][4];
            #pragma unroll
            for (int mt = 0; mt < 4; mt++)
                ldsm_x4(af[mt][0], af[mt][1], af[mt][2], af[mt][3],
                        as_u32 + 2u * ((wm + mt * 16 + lr) * AW + kk + lhi));
            uint32_t bf[4][2];
            #pragma unroll
            for (int nt2 = 0; nt2 < 2; nt2++) {
                uint32_t r0, r1, r2, r3;
                ldsm_x4_t(r0, r1, r2, r3,
                          bs_u32 + 2u * ((kk + lr) * BW + wn + nt2 * 16 + lhi));
                bf[2 * nt2][0] = r0;      bf[2 * nt2][1] = r1;
                bf[2 * nt2 + 1][0] = r2;  bf[2 * nt2 + 1][1] = r3;
            }
            #pragma unroll
            for (int mt = 0; mt < 4; mt++)
                #pragma unroll
                for (int nt = 0; nt < 4; nt++)
                    mma_f16(acc[mt][nt], af[mt][0], af[mt][1], af[mt][2], af[mt][3],
                            bf[nt][0], bf[nt][1]);
        }
        __syncthreads();
    }

    #pragma unroll
    for (int mt = 0; mt < 4; mt++) {
        int r = row0 + wm + mt * 16 + g;
        #pragma unroll
        for (int nt = 0; nt < 4; nt++) {
            int c = col0 + wn + nt * 8 + 2 * q;
            float bx = 0.f, by = 0.f;
            if (bias) { bx = bias[c]; by = bias[c + 1]; }
            float v0 = acc[mt][nt][0] + bx, v1 = acc[mt][nt][1] + by;
            float v2 = acc[mt][nt][2] + bx, v3 = acc[mt][nt][3] + by;
            if (out_half) {
                __half* Ch = (__half*)Cout;
                *(__half2*)(Ch + (size_t)r * N + c)       = __floats2half2_rn(v0, v1);
                *(__half2*)(Ch + (size_t)(r + 8) * N + c) = __floats2half2_rn(v2, v3);
            } else {
                float* Cf = (float*)Cout;
                *(float2*)(Cf + (size_t)r * N + c)       = make_float2(v0, v1);
                *(float2*)(Cf + (size_t)(r + 8) * N + c) = make_float2(v2, v3);
            }
        }
    }
}

// ---------------------------------------------------------------------------
// Flash attention (fp16 mma): round-11 structure (QT=128, 4 warps, 2 strips
// per warp, register-resident P, cp.async double-buffered K/V), with the
// softmax exponentials computed as packed fp16x2 (ex2.approx.f16x2):
// HALVES the MUFU work; the exp output IS the packed PV A-fragment.
// ---------------------------------------------------------------------------
#define QT  128
#define KT  64
#define FW  72    // halves per row
#define QTILE_H (QT * FW)
#define KTILE_H (KT * FW)
#define FLASH_SMEM_BYTES ((QTILE_H + 4 * KTILE_H) * 2)

__global__ __launch_bounds__(128)
void flash_f16(const __half* __restrict__ qkv, __half* __restrict__ out) {
    extern __shared__ __half smh[];
    uint32_t q_u32 = (uint32_t)__cvta_generic_to_shared(smh);
    uint32_t k_u32[2] = { q_u32 + 2u * QTILE_H,
                          q_u32 + 2u * (QTILE_H + KTILE_H) };
    uint32_t v_u32[2] = { q_u32 + 2u * (QTILE_H + 2 * KTILE_H),
                          q_u32 + 2u * (QTILE_H + 3 * KTILE_H) };

    int b  = blockIdx.z, h = blockIdx.y;
    int q0 = blockIdx.x * QT;
    int tid = threadIdx.x;
    int lane = tid & 31, wid = tid >> 5;
    int g = lane >> 2, qd = lane & 3;
    int m0 = wid * 16;
    uint32_t lr = lane & 15, lhi = (lane >> 4) * 8;

    uint32_t boffK = lr * FW + lhi;

    const __half* base = qkv + (size_t)b * SEQ * QKVW;
    int hc = h * DH;

    int cr = tid >> 1, ch = (tid & 1) << 5;

    // prefetch Q (128 rows) + tile-0 K/V (64 rows each)
    #pragma unroll
    for (int i2 = 0; i2 < 2; i2++) {
        int row = cr + 64 * i2;
        #pragma unroll
        for (int i = 0; i < 4; i++) {
            int off = ch + i * 8;
            cp_async16(q_u32 + 2u * (row * FW + off),
                       base + (size_t)(q0 + row) * QKVW + hc + off);
        }
    }
    #pragma unroll
    for (int i = 0; i < 4; i++) {
        int off = ch + i * 8;
        const __half* src = base + (size_t)cr * QKVW + hc + off;
        cp_async16(k_u32[0] + 2u * (cr * FW + off), src + DMODEL);
        cp_async16(v_u32[0] + 2u * (cr * FW + off), src + 2 * DMODEL);
    }
    cp_commit();

    float o[2][8][4] = {};
    uint32_t ap[2][16];
    float mr[2][2] = {{-INFINITY, -INFINITY}, {-INFINITY, -INFINITY}};
    float li[2][2] = {{0.f, 0.f}, {0.f, 0.f}};
    float al[2][2];

    const int NT = SEQ / KT;   // 32
    for (int kt = 0; kt < NT; kt++) {
        int buf = kt & 1;
        cp_wait_all();
        __syncthreads();

        if (kt + 1 < NT) {
            int nbuf = buf ^ 1;
            int k0n = (kt + 1) * KT;
            #pragma unroll
            for (int i = 0; i < 4; i++) {
                int off = ch + i * 8;
                const __half* src = base + (size_t)(k0n + cr) * QKVW + hc + off;
                cp_async16(k_u32[nbuf] + 2u * (cr * FW + off), src + DMODEL);
                cp_async16(v_u32[nbuf] + 2u * (cr * FW + off), src + 2 * DMODEL);
            }
            cp_commit();
        }

        // per strip: S = Qstrip @ K^T, softmax (fp16x2 exp), pack P
        #pragma unroll
        for (int st = 0; st < 2; st++) {
            uint32_t aoffQ = (st * 64 + m0 + lr) * FW + lhi;

            float s[8][4] = {};
            #pragma unroll
            for (int ks = 0; ks < 4; ks++) {
                int kk = ks * 16;
                uint32_t a0, a1, a2, a3;
                ldsm_x4(a0, a1, a2, a3, q_u32 + 2u * (aoffQ + kk));
                #pragma unroll
                for (int nt2 = 0; nt2 < 4; nt2++) {
                    uint32_t b0, b1, b2, b3;   // non-trans: pairs (b0,b2),(b1,b3)
                    ldsm_x4(b0, b1, b2, b3,
                            k_u32[buf] + 2u * (boffK + nt2 * 16 * FW + kk));
                    mma_f16(s[2 * nt2    ], a0, a1, a2, a3, b0, b2);
                    mma_f16(s[2 * nt2 + 1], a0, a1, a2, a3, b1, b3);
                }
            }

            // exp2-domain online softmax
            float mx0 = -INFINITY, mx1 = -INFINITY;
            #pragma unroll
            for (int nt = 0; nt < 8; nt++) {
                s[nt][0] *= SCL2; s[nt][1] *= SCL2;
                s[nt][2] *= SCL2; s[nt][3] *= SCL2;
                mx0 = fmaxf(mx0, fmaxf(s[nt][0], s[nt][1]));
                mx1 = fmaxf(mx1, fmaxf(s[nt][2], s[nt][3]));
            }
            #pragma unroll
            for (int w = 1; w < 4; w <<= 1) {
                mx0 = fmaxf(mx0, __shfl_xor_sync(0xffffffffu, mx0, w));
                mx1 = fmaxf(mx1, __shfl_xor_sync(0xffffffffu, mx1, w));
            }
            float mn0 = fmaxf(mr[st][0], mx0), mn1 = fmaxf(mr[st][1], mx1);
            al[st][0] = exp2f(mr[st][0] - mn0);
            al[st][1] = exp2f(mr[st][1] - mn1);
            mr[st][0] = mn0; mr[st][1] = mn1;

            // exp in packed fp16x2; result IS the PV A-fragment
            float sum0 = 0.f, sum1 = 0.f;
            #pragma unroll
            for (int nt = 0; nt < 8; nt++) {
                uint32_t p0 = h2exp2_pk(s[nt][0] - mn0, s[nt][1] - mn0);
                uint32_t p1 = h2exp2_pk(s[nt][2] - mn1, s[nt][3] - mn1);
                int idx = (nt >> 1) * 4 + (nt & 1) * 2;
                ap[st][idx]     = p0;
                ap[st][idx + 1] = p1;
                float2 f0 = __half22float2(*reinterpret_cast<__half2*>(&p0));
                float2 f1 = __half22float2(*reinterpret_cast<__half2*>(&p1));
                sum0 += f0.x + f0.y;
                sum1 += f1.x + f1.y;
            }
            #pragma unroll
            for (int w = 1; w < 4; w <<= 1) {
                sum0 += __shfl_xor_sync(0xffffffffu, sum0, w);
                sum1 += __shfl_xor_sync(0xffffffffu, sum1, w);
            }
            li[st][0] = li[st][0] * al[st][0] + sum0;
            li[st][1] = li[st][1] * al[st][1] + sum1;

            // rescale O strip
            #pragma unroll
            for (int nt = 0; nt < 8; nt++) {
                o[st][nt][0] *= al[st][0]; o[st][nt][1] *= al[st][0];
                o[st][nt][2] *= al[st][1]; o[st][nt][3] *= al[st][1];
            }
        }

        // PV: V B-frags loaded once, reused by both strips
        #pragma unroll
        for (int c2 = 0; c2 < 4; c2++) {
            int kk = c2 * 16;
            #pragma unroll
            for (int nt2 = 0; nt2 < 4; nt2++) {
                uint32_t b0, b1, b2, b3;   // trans: pairs (b0,b1),(b2,b3)
                ldsm_x4_t(b0, b1, b2, b3,
                          v_u32[buf] + 2u * ((kk + lr) * FW + nt2 * 16 + lhi));
                #pragma unroll
                for (int st = 0; st < 2; st++) {
                    mma_f16(o[st][2 * nt2    ], ap[st][c2*4+0], ap[st][c2*4+1],
                            ap[st][c2*4+2], ap[st][c2*4+3], b0, b1);
                    mma_f16(o[st][2 * nt2 + 1], ap[st][c2*4+0], ap[st][c2*4+1],
                            ap[st][c2*4+2], ap[st][c2*4+3], b2, b3);
                }
            }
        }
    }

    // normalize + write 'b n (h d)' as fp16
    #pragma unroll
    for (int st = 0; st < 2; st++) {
        float inv0 = 1.f / li[st][0], inv1 = 1.f / li[st][1];
        #pragma unroll
        for (int nt = 0; nt < 8; nt++) {
            int r = q0 + st * 64 + m0 + g;
            int c = hc + nt * 8 + 2 * qd;
            *(__half2*)(out + (size_t)((size_t)b * SEQ + r) * DMODEL + c) =
                __floats2half2_rn(o[st][nt][0] * inv0, o[st][nt][1] * inv0);
            *(__half2*)(out + (size_t)((size_t)b * SEQ + r + 8) * DMODEL + c) =
                __floats2half2_rn(o[st][nt][2] * inv1, o[st][nt][3] * inv1);
        }
    }
}

// ---------------------------------------------------------------------------
extern "C" void kernel_launch(void* const* d_in, const int* in_sizes, int n_in,
                              void* d_out, int out_size) {
    const float* x     = (const float*)d_in[0];
    const float* W_qkv = (const float*)d_in[1];
    const float* W_out = (const float*)d_in[2];
    const float* b_out = (const float*)d_in[3];
    float* out = (float*)d_out;

    __half *xh, *wqh, *woh, *qkv, *attn;
    cudaGetSymbolAddress((void**)&xh,   g_xh);
    cudaGetSymbolAddress((void**)&wqh,  g_wqh);
    cudaGetSymbolAddress((void**)&woh,  g_woh);
    cudaGetSymbolAddress((void**)&qkv,  g_qkv);
    cudaGetSymbolAddress((void**)&attn, g_attn);

    cudaFuncSetAttribute(flash_f16,
                         cudaFuncAttributeMaxDynamicSharedMemorySize,
                         FLASH_SMEM_BYTES);

    const int M = BATCH * SEQ;  // 8192
    const int NX = M * DMODEL, NWQ = DMODEL * QKVW, NWO = DMODEL * DMODEL;

    // 0) fp16 pre-conversion
    f32_to_f16<<<NX  / 1024, 256>>>(x,     xh,  NX);
    f32_to_f16<<<NWQ / 1024, 256>>>(W_qkv, wqh, NWQ);
    f32_to_f16<<<NWO / 1024, 256>>>(W_out, woh, NWO);

    // 1) qkv = x @ W_qkv  (fp16 out)
    gemm_f16<<<dim3(QKVW / BN, M / BM), 256>>>(
        xh, wqh, nullptr, qkv, M, QKVW, DMODEL, 1);

    // 2) attention (fp16 out)
    flash_f16<<<dim3(SEQ / QT, HEADS, BATCH), 128, FLASH_SMEM_BYTES>>>(
        qkv, attn);

    // 3) out = attn @ W_out + b_out  (fp32 out)
    gemm_f16<<<dim3(DMODEL / BN, M / BM), 256>>>(
        attn, woh, b_out, out, M, DMODEL, DMODEL, 0);
}